// round 9
// baseline (speedup 1.0000x reference)
#include <cuda_runtime.h>

// GCN 2-layer, scatter-reassociated + normalization-reassociated.
//
// t[d]  = dinv[d] * ( dinv[d]*x[d] + sum_e ew * dinv[s]*x[s] )
// out[d]= dinv[d] * ( dinv[d]*hw[d] + sum_e ew * dinv[s]*hw[s] ) + b2
//
// Proven shape (R6, 82.0us): 1 edge/thread flat grids, PDL between kernels.
// R3/R5/R8 all showed per-thread batching (vector, grid-stride, or scalar
// pairing) regresses: the edge passes are at the L1tex random-wavefront floor
// (5 random sector-ops/edge is the algorithmic minimum), and want maximal
// warp-level parallelism. R9: edge kernels at TPB=128 to halve block tail
// quantum; otherwise exact R6 memory shape (regs=16 edge kernels).

#define NMAX 131072
#define TPB_E 128
#define TPB_N 256

__device__ float  g_deg[NMAX];    // edge-weight sums; zeroed by k_node1 each call
__device__ float  g_dinv[NMAX];   // rsqrt(deg)
__device__ float2 g_xd[NMAX];     // dinv[i] * x[i]          (gather source)
__device__ float2 g_u[NMAX];      // scatter target layer 1  (init = xd)
__device__ float  g_hws[NMAX];    // dinv[i] * hw[i]         (gather source)

__device__ __forceinline__ void pdl_prologue() {
    cudaGridDependencySynchronize();            // wait for predecessor's writes
    cudaTriggerProgrammaticLaunchCompletion();  // let successor prelaunch early
}

// ---- kernel 1: deg[dst] += ew ----------------------------------------------
__global__ void __launch_bounds__(TPB_E) k_deg(const int* __restrict__ dst,
                                               const float* __restrict__ ew, int E) {
    pdl_prologue();
    int e = blockIdx.x * blockDim.x + threadIdx.x;
    if (e < E) atomicAdd(&g_deg[dst[e]], ew[e]);
}

// ---- kernel 2: dinv = rsqrt(deg+1); reset deg; xd = dinv*x; u init = xd ----
__global__ void __launch_bounds__(TPB_N) k_node1(const float2* __restrict__ x, int n) {
    pdl_prologue();
    int i = blockIdx.x * blockDim.x + threadIdx.x;
    if (i >= n) return;
    float d = g_deg[i] + 1.0f;      // +1: self-loop weight; always > 0
    g_deg[i] = 0.0f;                // reset for next graph replay
    float r = rsqrtf(d);
    g_dinv[i] = r;
    float2 xv = x[i];
    float2 xd = make_float2(r * xv.x, r * xv.y);
    g_xd[i] = xd;
    g_u[i]  = xd;   // self-loop term (outer dinv applied later)
}

// ---- kernel 3: layer-1 edge scatter: u[d] += ew * xd[s] ---------------------
__global__ void __launch_bounds__(TPB_E) k_edge1(const int* __restrict__ src,
                                                 const int* __restrict__ dst,
                                                 const float* __restrict__ ew, int E) {
    pdl_prologue();
    int e = blockIdx.x * blockDim.x + threadIdx.x;
    if (e >= E) return;
    int s = src[e];
    int d = dst[e];
    float w = ew[e];
    float2 xd = __ldg(&g_xd[s]);
    float a = w * xd.x;
    float b = w * xd.y;
    asm volatile("red.global.add.v2.f32 [%0], {%1, %2};"
                 :: "l"(&g_u[d]), "f"(a), "f"(b) : "memory");
}

// ---- kernel 4: t = dinv*u; MLP; hws = dinv*hw; out init = hws ---------------
__global__ void __launch_bounds__(TPB_N) k_node2(const float4* __restrict__ W1,  // [2,16] as 8 float4
                                                 const float4* __restrict__ b1,  // [16]   as 4 float4
                                                 const float4* __restrict__ W2,  // [16]   as 4 float4
                                                 float* __restrict__ out, int n) {
    pdl_prologue();
    int i = blockIdx.x * blockDim.x + threadIdx.x;
    if (i >= n) return;
    float r = g_dinv[i];
    float2 u = g_u[i];
    float tx = r * u.x;
    float ty = r * u.y;
    float acc = 0.0f;
#pragma unroll
    for (int q = 0; q < 4; q++) {
        float4 w1a = __ldg(&W1[q]);        // W1[0][4q..4q+3]
        float4 w1b = __ldg(&W1[4 + q]);    // W1[1][4q..4q+3]
        float4 bb  = __ldg(&b1[q]);
        float4 w2  = __ldg(&W2[q]);
        float h0 = fmaxf(fmaf(tx, w1a.x, fmaf(ty, w1b.x, bb.x)), 0.0f);
        float h1 = fmaxf(fmaf(tx, w1a.y, fmaf(ty, w1b.y, bb.y)), 0.0f);
        float h2 = fmaxf(fmaf(tx, w1a.z, fmaf(ty, w1b.z, bb.z)), 0.0f);
        float h3 = fmaxf(fmaf(tx, w1a.w, fmaf(ty, w1b.w, bb.w)), 0.0f);
        acc = fmaf(h0, w2.x, fmaf(h1, w2.y, fmaf(h2, w2.z, fmaf(h3, w2.w, acc))));
    }
    float hws = r * acc;
    g_hws[i] = hws;
    out[i]   = hws;   // self-loop init (outer dinv + b2 applied in k_node3)
}

// ---- kernel 5: layer-2 edge scatter: out[d] += ew * hws[s] ------------------
__global__ void __launch_bounds__(TPB_E) k_edge2(const int* __restrict__ src,
                                                 const int* __restrict__ dst,
                                                 const float* __restrict__ ew,
                                                 float* __restrict__ out, int E) {
    pdl_prologue();
    int e = blockIdx.x * blockDim.x + threadIdx.x;
    if (e >= E) return;
    int s = src[e];
    int d = dst[e];
    atomicAdd(&out[d], ew[e] * __ldg(&g_hws[s]));
}

// ---- kernel 6: out = dinv*out + b2 ------------------------------------------
__global__ void __launch_bounds__(TPB_N) k_node3(const float* __restrict__ b2,
                                                 float* __restrict__ out, int n) {
    pdl_prologue();
    int i = blockIdx.x * blockDim.x + threadIdx.x;
    if (i >= n) return;
    out[i] = fmaf(g_dinv[i], out[i], __ldg(&b2[0]));
}

// ---- host: launch all kernels with programmatic stream serialization --------
template <typename F, typename... Args>
static void launch_pdl(F kernel, int nblocks, int tpb, Args... args) {
    cudaLaunchConfig_t cfg = {};
    cfg.gridDim  = dim3((unsigned)nblocks, 1, 1);
    cfg.blockDim = dim3((unsigned)tpb, 1, 1);
    cfg.dynamicSmemBytes = 0;
    cfg.stream = 0;
    cudaLaunchAttribute attr[1];
    attr[0].id = cudaLaunchAttributeProgrammaticStreamSerialization;
    attr[0].val.programmaticStreamSerializationAllowed = 1;
    cfg.attrs = attr;
    cfg.numAttrs = 1;
    cudaLaunchKernelEx(&cfg, kernel, args...);
}

extern "C" void kernel_launch(void* const* d_in, const int* in_sizes, int n_in,
                              void* d_out, int out_size) {
    const float* x  = (const float*)d_in[0];   // [N, 2]
    const int*   ei = (const int*)d_in[1];     // [2, E]
    const float* ew = (const float*)d_in[2];   // [E]
    const float* W1 = (const float*)d_in[3];   // [2, 16]
    const float* b1 = (const float*)d_in[4];   // [16]
    const float* W2 = (const float*)d_in[5];   // [16, 1]
    const float* b2 = (const float*)d_in[6];   // [1]
    float* out = (float*)d_out;                // [N, 1]

    int n = in_sizes[0] / 2;
    int E = in_sizes[2];
    const int* src = ei;
    const int* dst = ei + E;

    int nb_n = (n + TPB_N - 1) / TPB_N;
    int nb_e = (E + TPB_E - 1) / TPB_E;

    launch_pdl(k_deg,   nb_e, TPB_E, dst, ew, E);
    launch_pdl(k_node1, nb_n, TPB_N, (const float2*)x, n);
    launch_pdl(k_edge1, nb_e, TPB_E, src, dst, ew, E);
    launch_pdl(k_node2, nb_n, TPB_N, (const float4*)W1, (const float4*)b1,
                              (const float4*)W2, out, n);
    launch_pdl(k_edge2, nb_e, TPB_E, src, dst, ew, out, E);
    launch_pdl(k_node3, nb_n, TPB_N, b2, out, n);
}

// round 10
// speedup vs baseline: 1.0902x; 1.0902x over previous
#include <cuda_runtime.h>

// GCN 2-layer, scatter-reassociated + normalization-reassociated.
//
// t[d]  = dinv[d] * ( dinv[d]*x[d] + sum_e ew * dinv[s]*x[s] )
// out[d]= dinv[d] * ( dinv[d]*hw[d] + sum_e ew * dinv[s]*hw[s] ) + b2
//
// Proven shape (R6, 82.0us): 1 edge/thread flat TPB=256 grids, PDL.
// R3/R5/R8/R9 established the edge passes sit at the L1tex random-wavefront
// floor and want this exact shape.
//
// R10: PDL prologue split. Streaming loads (src/dst/ew — pure inputs, never
// written by any kernel) are issued BEFORE cudaGridDependencySynchronize();
// only the predecessor-dependent random gathers/scatters wait. Prelaunched
// blocks overlap stream-load latency with the predecessor's tail. k_deg has
// no dependence on its immediate predecessor (prev replay's k_node3 only
// touches `out`; g_deg reset is 2+ kernels upstream, outside PDL's one-deep
// overlap) so it drops the grid-sync entirely.

#define NMAX 131072
#define TPB 256

__device__ float  g_deg[NMAX];    // edge-weight sums; zeroed by k_node1 each call
__device__ float  g_dinv[NMAX];   // rsqrt(deg)
__device__ float2 g_xd[NMAX];     // dinv[i] * x[i]          (gather source)
__device__ float2 g_u[NMAX];      // scatter target layer 1  (init = xd)
__device__ float  g_hws[NMAX];    // dinv[i] * hw[i]         (gather source)

// ---- kernel 1: deg[dst] += ew  (no grid-sync: independent of predecessor) --
__global__ void __launch_bounds__(TPB) k_deg(const int* __restrict__ dst,
                                             const float* __restrict__ ew, int E) {
    cudaTriggerProgrammaticLaunchCompletion();
    int e = blockIdx.x * blockDim.x + threadIdx.x;
    if (e < E) atomicAdd(&g_deg[dst[e]], ew[e]);
}

// ---- kernel 2: dinv = rsqrt(deg+1); reset deg; xd = dinv*x; u init = xd ----
__global__ void __launch_bounds__(TPB) k_node1(const float2* __restrict__ x, int n) {
    int i = blockIdx.x * blockDim.x + threadIdx.x;
    float2 xv;
    if (i < n) xv = x[i];                       // pure input: prefetch pre-sync
    cudaGridDependencySynchronize();            // wait for k_deg's atomics
    cudaTriggerProgrammaticLaunchCompletion();
    if (i >= n) return;
    float d = g_deg[i] + 1.0f;      // +1: self-loop weight; always > 0
    g_deg[i] = 0.0f;                // reset for next graph replay
    float r = rsqrtf(d);
    g_dinv[i] = r;
    float2 xd = make_float2(r * xv.x, r * xv.y);
    g_xd[i] = xd;
    g_u[i]  = xd;   // self-loop term (outer dinv applied later)
}

// ---- kernel 3: layer-1 edge scatter: u[d] += ew * xd[s] ---------------------
__global__ void __launch_bounds__(TPB) k_edge1(const int* __restrict__ src,
                                               const int* __restrict__ dst,
                                               const float* __restrict__ ew, int E) {
    int e = blockIdx.x * blockDim.x + threadIdx.x;
    int s = 0, d = 0;
    float w = 0.0f;
    if (e < E) {                                // pure inputs: prefetch pre-sync
        s = src[e];
        d = dst[e];
        w = ew[e];
    }
    cudaGridDependencySynchronize();            // wait for k_node1's g_xd/g_u
    cudaTriggerProgrammaticLaunchCompletion();
    if (e >= E) return;
    float2 xd = __ldg(&g_xd[s]);
    float a = w * xd.x;
    float b = w * xd.y;
    asm volatile("red.global.add.v2.f32 [%0], {%1, %2};"
                 :: "l"(&g_u[d]), "f"(a), "f"(b) : "memory");
}

// ---- kernel 4: t = dinv*u; MLP; hws = dinv*hw; out init = hws ---------------
__global__ void __launch_bounds__(TPB) k_node2(const float4* __restrict__ W1,  // [2,16] as 8 float4
                                               const float4* __restrict__ b1,  // [16]   as 4 float4
                                               const float4* __restrict__ W2,  // [16]   as 4 float4
                                               float* __restrict__ out, int n) {
    cudaGridDependencySynchronize();            // wait for k_edge1's g_u
    cudaTriggerProgrammaticLaunchCompletion();
    int i = blockIdx.x * blockDim.x + threadIdx.x;
    if (i >= n) return;
    float r = g_dinv[i];
    float2 u = g_u[i];
    float tx = r * u.x;
    float ty = r * u.y;
    float acc = 0.0f;
#pragma unroll
    for (int q = 0; q < 4; q++) {
        float4 w1a = __ldg(&W1[q]);        // W1[0][4q..4q+3]
        float4 w1b = __ldg(&W1[4 + q]);    // W1[1][4q..4q+3]
        float4 bb  = __ldg(&b1[q]);
        float4 w2  = __ldg(&W2[q]);
        float h0 = fmaxf(fmaf(tx, w1a.x, fmaf(ty, w1b.x, bb.x)), 0.0f);
        float h1 = fmaxf(fmaf(tx, w1a.y, fmaf(ty, w1b.y, bb.y)), 0.0f);
        float h2 = fmaxf(fmaf(tx, w1a.z, fmaf(ty, w1b.z, bb.z)), 0.0f);
        float h3 = fmaxf(fmaf(tx, w1a.w, fmaf(ty, w1b.w, bb.w)), 0.0f);
        acc = fmaf(h0, w2.x, fmaf(h1, w2.y, fmaf(h2, w2.z, fmaf(h3, w2.w, acc))));
    }
    float hws = r * acc;
    g_hws[i] = hws;
    out[i]   = hws;   // self-loop init (outer dinv + b2 applied in k_node3)
}

// ---- kernel 5: layer-2 edge scatter: out[d] += ew * hws[s] ------------------
__global__ void __launch_bounds__(TPB) k_edge2(const int* __restrict__ src,
                                               const int* __restrict__ dst,
                                               const float* __restrict__ ew,
                                               float* __restrict__ out, int E) {
    int e = blockIdx.x * blockDim.x + threadIdx.x;
    int s = 0, d = 0;
    float w = 0.0f;
    if (e < E) {                                // pure inputs: prefetch pre-sync
        s = src[e];
        d = dst[e];
        w = ew[e];
    }
    cudaGridDependencySynchronize();            // wait for k_node2's g_hws/out
    cudaTriggerProgrammaticLaunchCompletion();
    if (e >= E) return;
    atomicAdd(&out[d], w * __ldg(&g_hws[s]));
}

// ---- kernel 6: out = dinv*out + b2 ------------------------------------------
__global__ void __launch_bounds__(TPB) k_node3(const float* __restrict__ b2,
                                               float* __restrict__ out, int n) {
    cudaGridDependencySynchronize();            // wait for k_edge2's out atomics
    cudaTriggerProgrammaticLaunchCompletion();
    int i = blockIdx.x * blockDim.x + threadIdx.x;
    if (i >= n) return;
    out[i] = fmaf(g_dinv[i], out[i], __ldg(&b2[0]));
}

// ---- host: launch all kernels with programmatic stream serialization --------
template <typename F, typename... Args>
static void launch_pdl(F kernel, int nblocks, Args... args) {
    cudaLaunchConfig_t cfg = {};
    cfg.gridDim  = dim3((unsigned)nblocks, 1, 1);
    cfg.blockDim = dim3(TPB, 1, 1);
    cfg.dynamicSmemBytes = 0;
    cfg.stream = 0;
    cudaLaunchAttribute attr[1];
    attr[0].id = cudaLaunchAttributeProgrammaticStreamSerialization;
    attr[0].val.programmaticStreamSerializationAllowed = 1;
    cfg.attrs = attr;
    cfg.numAttrs = 1;
    cudaLaunchKernelEx(&cfg, kernel, args...);
}

extern "C" void kernel_launch(void* const* d_in, const int* in_sizes, int n_in,
                              void* d_out, int out_size) {
    const float* x  = (const float*)d_in[0];   // [N, 2]
    const int*   ei = (const int*)d_in[1];     // [2, E]
    const float* ew = (const float*)d_in[2];   // [E]
    const float* W1 = (const float*)d_in[3];   // [2, 16]
    const float* b1 = (const float*)d_in[4];   // [16]
    const float* W2 = (const float*)d_in[5];   // [16, 1]
    const float* b2 = (const float*)d_in[6];   // [1]
    float* out = (float*)d_out;                // [N, 1]

    int n = in_sizes[0] / 2;
    int E = in_sizes[2];
    const int* src = ei;
    const int* dst = ei + E;

    int nb_n = (n + TPB - 1) / TPB;
    int nb_e = (E + TPB - 1) / TPB;

    launch_pdl(k_deg,   nb_e, dst, ew, E);
    launch_pdl(k_node1, nb_n, (const float2*)x, n);
    launch_pdl(k_edge1, nb_e, src, dst, ew, E);
    launch_pdl(k_node2, nb_n, (const float4*)W1, (const float4*)b1,
                              (const float4*)W2, out, n);
    launch_pdl(k_edge2, nb_e, src, dst, ew, out, E);
    launch_pdl(k_node3, nb_n, b2, out, n);
}

// round 11
// speedup vs baseline: 1.1000x; 1.0090x over previous
#include <cuda_runtime.h>

// GCN 2-layer, scatter-reassociated + normalization-reassociated.
//
// t[d]  = dinv[d] * ( dinv[d]*x[d] + sum_e ew * dinv[s]*x[s] )
// out[d]= dinv[d] * ( dinv[d]*hw[d] + sum_e ew * dinv[s]*hw[s] ) + b2
//
// Final shape = R6 (best measured, 82.0us): 1 edge/thread flat TPB=256 grids,
// PDL between kernels, minimal edge-kernel bodies (regs=16).
// Measured and rejected: 4-edge vector (R3), grid-stride persistent (R5),
// L1 cache-policy hints (R7), 2-edge scalar pairing (R8), TPB=128 (R9),
// prefetch-before-sync (R10). Edge passes sit at ~90% of the L1tex
// random-wavefront floor (5 random sector-ops/edge = algorithmic minimum).
//
// R11 delta vs R6: k_deg drops cudaGridDependencySynchronize — it has no
// data dependence on its predecessor (prev replay's k_node3 writes only
// `out`; g_deg's reset is 2+ kernels upstream, beyond PDL's one-deep
// overlap), so its blocks dispatch during the predecessor's tail.

#define NMAX 131072
#define TPB 256

__device__ float  g_deg[NMAX];    // edge-weight sums; zeroed by k_node1 each call
__device__ float  g_dinv[NMAX];   // rsqrt(deg)
__device__ float2 g_xd[NMAX];     // dinv[i] * x[i]          (gather source)
__device__ float2 g_u[NMAX];      // scatter target layer 1  (init = xd)
__device__ float  g_hws[NMAX];    // dinv[i] * hw[i]         (gather source)

__device__ __forceinline__ void pdl_prologue() {
    cudaGridDependencySynchronize();            // wait for predecessor's writes
    cudaTriggerProgrammaticLaunchCompletion();  // let successor prelaunch early
}

// ---- kernel 1: deg[dst] += ew  (no grid-sync: independent of predecessor) --
__global__ void __launch_bounds__(TPB) k_deg(const int* __restrict__ dst,
                                             const float* __restrict__ ew, int E) {
    cudaTriggerProgrammaticLaunchCompletion();
    int e = blockIdx.x * blockDim.x + threadIdx.x;
    if (e < E) atomicAdd(&g_deg[dst[e]], ew[e]);
}

// ---- kernel 2: dinv = rsqrt(deg+1); reset deg; xd = dinv*x; u init = xd ----
__global__ void __launch_bounds__(TPB) k_node1(const float2* __restrict__ x, int n) {
    pdl_prologue();
    int i = blockIdx.x * blockDim.x + threadIdx.x;
    if (i >= n) return;
    float d = g_deg[i] + 1.0f;      // +1: self-loop weight; always > 0
    g_deg[i] = 0.0f;                // reset for next graph replay
    float r = rsqrtf(d);
    g_dinv[i] = r;
    float2 xv = x[i];
    float2 xd = make_float2(r * xv.x, r * xv.y);
    g_xd[i] = xd;
    g_u[i]  = xd;   // self-loop term (outer dinv applied later)
}

// ---- kernel 3: layer-1 edge scatter: u[d] += ew * xd[s] ---------------------
__global__ void __launch_bounds__(TPB) k_edge1(const int* __restrict__ src,
                                               const int* __restrict__ dst,
                                               const float* __restrict__ ew, int E) {
    pdl_prologue();
    int e = blockIdx.x * blockDim.x + threadIdx.x;
    if (e >= E) return;
    int s = src[e];
    int d = dst[e];
    float w = ew[e];
    float2 xd = __ldg(&g_xd[s]);
    float a = w * xd.x;
    float b = w * xd.y;
    asm volatile("red.global.add.v2.f32 [%0], {%1, %2};"
                 :: "l"(&g_u[d]), "f"(a), "f"(b) : "memory");
}

// ---- kernel 4: t = dinv*u; MLP; hws = dinv*hw; out init = hws ---------------
__global__ void __launch_bounds__(TPB) k_node2(const float4* __restrict__ W1,  // [2,16] as 8 float4
                                               const float4* __restrict__ b1,  // [16]   as 4 float4
                                               const float4* __restrict__ W2,  // [16]   as 4 float4
                                               float* __restrict__ out, int n) {
    pdl_prologue();
    int i = blockIdx.x * blockDim.x + threadIdx.x;
    if (i >= n) return;
    float r = g_dinv[i];
    float2 u = g_u[i];
    float tx = r * u.x;
    float ty = r * u.y;
    float acc = 0.0f;
#pragma unroll
    for (int q = 0; q < 4; q++) {
        float4 w1a = __ldg(&W1[q]);        // W1[0][4q..4q+3]
        float4 w1b = __ldg(&W1[4 + q]);    // W1[1][4q..4q+3]
        float4 bb  = __ldg(&b1[q]);
        float4 w2  = __ldg(&W2[q]);
        float h0 = fmaxf(fmaf(tx, w1a.x, fmaf(ty, w1b.x, bb.x)), 0.0f);
        float h1 = fmaxf(fmaf(tx, w1a.y, fmaf(ty, w1b.y, bb.y)), 0.0f);
        float h2 = fmaxf(fmaf(tx, w1a.z, fmaf(ty, w1b.z, bb.z)), 0.0f);
        float h3 = fmaxf(fmaf(tx, w1a.w, fmaf(ty, w1b.w, bb.w)), 0.0f);
        acc = fmaf(h0, w2.x, fmaf(h1, w2.y, fmaf(h2, w2.z, fmaf(h3, w2.w, acc))));
    }
    float hws = r * acc;
    g_hws[i] = hws;
    out[i]   = hws;   // self-loop init (outer dinv + b2 applied in k_node3)
}

// ---- kernel 5: layer-2 edge scatter: out[d] += ew * hws[s] ------------------
__global__ void __launch_bounds__(TPB) k_edge2(const int* __restrict__ src,
                                               const int* __restrict__ dst,
                                               const float* __restrict__ ew,
                                               float* __restrict__ out, int E) {
    pdl_prologue();
    int e = blockIdx.x * blockDim.x + threadIdx.x;
    if (e >= E) return;
    int s = src[e];
    int d = dst[e];
    atomicAdd(&out[d], ew[e] * __ldg(&g_hws[s]));
}

// ---- kernel 6: out = dinv*out + b2 ------------------------------------------
__global__ void __launch_bounds__(TPB) k_node3(const float* __restrict__ b2,
                                               float* __restrict__ out, int n) {
    pdl_prologue();
    int i = blockIdx.x * blockDim.x + threadIdx.x;
    if (i >= n) return;
    out[i] = fmaf(g_dinv[i], out[i], __ldg(&b2[0]));
}

// ---- host: launch all kernels with programmatic stream serialization --------
template <typename F, typename... Args>
static void launch_pdl(F kernel, int nblocks, Args... args) {
    cudaLaunchConfig_t cfg = {};
    cfg.gridDim  = dim3((unsigned)nblocks, 1, 1);
    cfg.blockDim = dim3(TPB, 1, 1);
    cfg.dynamicSmemBytes = 0;
    cfg.stream = 0;
    cudaLaunchAttribute attr[1];
    attr[0].id = cudaLaunchAttributeProgrammaticStreamSerialization;
    attr[0].val.programmaticStreamSerializationAllowed = 1;
    cfg.attrs = attr;
    cfg.numAttrs = 1;
    cudaLaunchKernelEx(&cfg, kernel, args...);
}

extern "C" void kernel_launch(void* const* d_in, const int* in_sizes, int n_in,
                              void* d_out, int out_size) {
    const float* x  = (const float*)d_in[0];   // [N, 2]
    const int*   ei = (const int*)d_in[1];     // [2, E]
    const float* ew = (const float*)d_in[2];   // [E]
    const float* W1 = (const float*)d_in[3];   // [2, 16]
    const float* b1 = (const float*)d_in[4];   // [16]
    const float* W2 = (const float*)d_in[5];   // [16, 1]
    const float* b2 = (const float*)d_in[6];   // [1]
    float* out = (float*)d_out;                // [N, 1]

    int n = in_sizes[0] / 2;
    int E = in_sizes[2];
    const int* src = ei;
    const int* dst = ei + E;

    int nb_n = (n + TPB - 1) / TPB;
    int nb_e = (E + TPB - 1) / TPB;

    launch_pdl(k_deg,   nb_e, dst, ew, E);
    launch_pdl(k_node1, nb_n, (const float2*)x, n);
    launch_pdl(k_edge1, nb_e, src, dst, ew, E);
    launch_pdl(k_node2, nb_n, (const float4*)W1, (const float4*)b1,
                              (const float4*)W2, out, n);
    launch_pdl(k_edge2, nb_e, src, dst, ew, out, E);
    launch_pdl(k_node3, nb_n, b2, out, n);
}